// round 3
// baseline (speedup 1.0000x reference)
#include <cuda_runtime.h>
#include <math.h>

// Problem constants
#define MROWS  131072          // B * H * W = 32 * 64 * 64
#define CDIM   256
#define DFF    1024
#define NWIN   2048            // B * 64 windows
#define NHEAD  8

// ---------------- scratch ---------------------------------------------------
__device__ float g_xw  [(size_t)MROWS * CDIM];
__device__ float g_qkv [(size_t)MROWS * 768];
__device__ float g_attn[(size_t)MROWS * CDIM];
__device__ float g_hs  [(size_t)MROWS * CDIM];
__device__ float g_ff  [(size_t)MROWS * DFF];
__device__ float g_wqkv[256 * 768];
__device__ float g_bqkv[768];

// ---------------- tf32 helper ----------------------------------------------
__device__ __forceinline__ unsigned f2tf(float x) {
    unsigned r;
    asm("cvt.rna.tf32.f32 %0, %1;" : "=r"(r) : "f"(x));
    return r;
}

// ---------------- LayerNorm (+ optional shift/window partition) -------------
__global__ void ln_kernel(const float* __restrict__ x, float* __restrict__ y,
                          const float* __restrict__ gam, const float* __restrict__ bet,
                          int shift)
{
    int w    = (blockIdx.x * blockDim.x + threadIdx.x) >> 5;
    int lane = threadIdx.x & 31;
    if (w >= MROWS) return;

    size_t src;
    if (shift) {
        int b_  = w >> 12;
        int rem = w & 4095;
        int wi  = rem >> 6;
        int t   = rem & 63;
        int hp  = ((wi >> 3) << 3) + (t >> 3);
        int wp  = ((wi & 7)  << 3) + (t & 7);
        int sh  = (hp + 4) & 63;
        int sw  = (wp + 4) & 63;
        src = ((size_t)b_ * 4096 + sh * 64 + sw) * CDIM;
    } else {
        src = (size_t)w * CDIM;
    }

    float4 v0 = *(const float4*)(x + src + lane * 4);
    float4 v1 = *(const float4*)(x + src + 128 + lane * 4);

    float s  = v0.x + v0.y + v0.z + v0.w + v1.x + v1.y + v1.z + v1.w;
    float s2 = v0.x*v0.x + v0.y*v0.y + v0.z*v0.z + v0.w*v0.w
             + v1.x*v1.x + v1.y*v1.y + v1.z*v1.z + v1.w*v1.w;
    #pragma unroll
    for (int o = 16; o; o >>= 1) {
        s  += __shfl_xor_sync(0xffffffffu, s,  o);
        s2 += __shfl_xor_sync(0xffffffffu, s2, o);
    }
    float mean = s * (1.f / 256.f);
    float var  = s2 * (1.f / 256.f) - mean * mean;
    float rs   = rsqrtf(var + 1e-5f);

    float4 g0 = *(const float4*)(gam + lane * 4);
    float4 g1 = *(const float4*)(gam + 128 + lane * 4);
    float4 b0 = *(const float4*)(bet + lane * 4);
    float4 b1 = *(const float4*)(bet + 128 + lane * 4);

    float4 o0, o1;
    o0.x = (v0.x - mean) * rs * g0.x + b0.x;
    o0.y = (v0.y - mean) * rs * g0.y + b0.y;
    o0.z = (v0.z - mean) * rs * g0.z + b0.z;
    o0.w = (v0.w - mean) * rs * g0.w + b0.w;
    o1.x = (v1.x - mean) * rs * g1.x + b1.x;
    o1.y = (v1.y - mean) * rs * g1.y + b1.y;
    o1.z = (v1.z - mean) * rs * g1.z + b1.z;
    o1.w = (v1.w - mean) * rs * g1.w + b1.w;

    *(float4*)(y + (size_t)w * CDIM + lane * 4)       = o0;
    *(float4*)(y + (size_t)w * CDIM + 128 + lane * 4) = o1;
}

// ---------------- pack wq|wk|wv ---------------------------------------------
__global__ void pack_qkv_kernel(const float* __restrict__ wq, const float* __restrict__ wk,
                                const float* __restrict__ wv, const float* __restrict__ bq,
                                const float* __restrict__ bk, const float* __restrict__ bv,
                                float* __restrict__ w, float* __restrict__ b)
{
    int i = blockIdx.x * blockDim.x + threadIdx.x;   // 0..65535
    int k = i >> 8, n = i & 255;
    w[k * 768 + n]       = wq[i];
    w[k * 768 + 256 + n] = wk[i];
    w[k * 768 + 512 + n] = wv[i];
    if (k == 0) { b[n] = bq[n]; b[n + 256] = bk[n]; b[n + 512] = bv[n]; }
}

// ---------------- fused window attention ------------------------------------
__global__ void __launch_bounds__(64)
attn_kernel(const float* __restrict__ qkv, const float* __restrict__ bt,
            float* __restrict__ out)
{
    __shared__ float kS[64][32];
    __shared__ float vS[64][32];
    __shared__ float sS[64][65];
    __shared__ int   lab[64];

    int bx  = blockIdx.x;
    int win = bx >> 3;
    int h   = bx & 7;
    int t   = threadIdx.x;

    int r0 = t >> 3, c0 = t & 7;
    int hp = (((win >> 3) & 7) << 3) + r0;
    int wp = ((win & 7) << 3) + c0;
    lab[t] = (hp < 56 ? 0 : (hp < 60 ? 1 : 2)) * 3
           + (wp < 56 ? 0 : (wp < 60 ? 1 : 2));

    const float* base = qkv + (size_t)(win * 64 + t) * 768;
    float q[32];
    #pragma unroll
    for (int i = 0; i < 8; i++) ((float4*)q)[i] = *(const float4*)(base + h * 32 + i * 4);
    #pragma unroll
    for (int i = 0; i < 8; i++) *(float4*)&kS[t][i * 4] = *(const float4*)(base + 256 + h * 32 + i * 4);
    #pragma unroll
    for (int i = 0; i < 8; i++) *(float4*)&vS[t][i * 4] = *(const float4*)(base + 512 + h * 32 + i * 4);
    __syncthreads();

    const float scale = 0.1767766952966369f;
    float mx = -1e30f;
    int myLab = lab[t];
    for (int m = 0; m < 64; m++) {
        float d = 0.f;
        #pragma unroll
        for (int dd = 0; dd < 32; dd += 4) {
            float4 kv = *(const float4*)&kS[m][dd];
            d += q[dd] * kv.x + q[dd+1] * kv.y + q[dd+2] * kv.z + q[dd+3] * kv.w;
        }
        int r1 = m >> 3, c1 = m & 7;
        int idx = (r0 - r1 + 7) * 15 + (c0 - c1 + 7);
        float s = d * scale + bt[idx * 8 + h];
        if (myLab != lab[m]) s -= 100.f;
        sS[t][m] = s;
        mx = fmaxf(mx, s);
    }
    float sum = 0.f;
    for (int m = 0; m < 64; m++) {
        float e = __expf(sS[t][m] - mx);
        sS[t][m] = e;
        sum += e;
    }
    float inv = 1.f / sum;

    float acc[32];
    #pragma unroll
    for (int dd = 0; dd < 32; dd++) acc[dd] = 0.f;
    for (int m = 0; m < 64; m++) {
        float p = sS[t][m] * inv;
        #pragma unroll
        for (int dd = 0; dd < 32; dd += 4) {
            float4 vv = *(const float4*)&vS[m][dd];
            acc[dd]   += p * vv.x;
            acc[dd+1] += p * vv.y;
            acc[dd+2] += p * vv.z;
            acc[dd+3] += p * vv.w;
        }
    }
    float* o = out + (size_t)(win * 64 + t) * 256 + h * 32;
    #pragma unroll
    for (int i = 0; i < 8; i++) *(float4*)(o + i * 4) = ((float4*)acc)[i];
}

// ---------------- tf32 tensor-core GEMM with fused epilogues ----------------
// C(M,N) = A(M,K) @ B(K,N), row-major, fp32 in/out, tf32 mma accumulate fp32.
// Block tile 128x256, 8 warps, each warp 64x64 (4 m-frags x 8 n-frags), BK=16.
// MODE 0: + bias                          -> Cout (ldc)
// MODE 1: + bias + window-reverse/roll + shortcut(aux) -> image layout
// MODE 2: gelu(. + bias)                  -> Cout (ldc)
// MODE 3: + bias + aux[row]               -> Cout (ldc=256)
template<int MODE>
__global__ void __launch_bounds__(256, 1)
mma_gemm(const float* __restrict__ A, const float* __restrict__ Bw,
         const float* __restrict__ bias, float* __restrict__ Cout,
         int K, int ldb, int ldc, const float* __restrict__ aux)
{
    __shared__ unsigned As[128 * 20];   // [row][k], stride 20 (conflict-free frag loads)
    __shared__ unsigned Bs[16 * 264];   // [k][n],  stride 264

    int tid  = threadIdx.x;
    int lane = tid & 31, wid = tid >> 5;
    int g  = lane >> 2, tg = lane & 3;
    int wm = (wid & 1) * 64;
    int wn = (wid >> 1) * 64;
    int m0 = blockIdx.y * 128;
    int n0 = blockIdx.x * 256;

    float acc[4][8][4];
    #pragma unroll
    for (int mi = 0; mi < 4; mi++)
        #pragma unroll
        for (int ni = 0; ni < 8; ni++)
            #pragma unroll
            for (int r = 0; r < 4; r++) acc[mi][ni][r] = 0.f;

    int arow = tid >> 1, acol = (tid & 1) * 8;
    const float* Abase = A + (size_t)(m0 + arow) * K + acol;

    for (int k0 = 0; k0 < K; k0 += 16) {
        // global staging (overlaps previous tile's compute)
        float4 av0 = *(const float4*)(Abase + k0);
        float4 av1 = *(const float4*)(Abase + k0 + 4);
        float4 bv[4];
        #pragma unroll
        for (int i = 0; i < 4; i++) {
            int lin = tid + i * 256;
            int br = lin >> 6, bc = (lin & 63) * 4;
            bv[i] = *(const float4*)(Bw + (size_t)(k0 + br) * ldb + n0 + bc);
        }
        __syncthreads();
        {
            unsigned* ap = As + arow * 20 + acol;
            ap[0] = f2tf(av0.x); ap[1] = f2tf(av0.y); ap[2] = f2tf(av0.z); ap[3] = f2tf(av0.w);
            ap[4] = f2tf(av1.x); ap[5] = f2tf(av1.y); ap[6] = f2tf(av1.z); ap[7] = f2tf(av1.w);
            #pragma unroll
            for (int i = 0; i < 4; i++) {
                int lin = tid + i * 256;
                int br = lin >> 6, bc = (lin & 63) * 4;
                unsigned* bp = Bs + br * 264 + bc;
                bp[0] = f2tf(bv[i].x); bp[1] = f2tf(bv[i].y);
                bp[2] = f2tf(bv[i].z); bp[3] = f2tf(bv[i].w);
            }
        }
        __syncthreads();

        #pragma unroll
        for (int kf = 0; kf < 2; kf++) {
            int kb = kf * 8;
            unsigned af[4][4];
            #pragma unroll
            for (int mi = 0; mi < 4; mi++) {
                int r = wm + mi * 16 + g;
                af[mi][0] = As[r * 20 + kb + tg];
                af[mi][1] = As[(r + 8) * 20 + kb + tg];
                af[mi][2] = As[r * 20 + kb + tg + 4];
                af[mi][3] = As[(r + 8) * 20 + kb + tg + 4];
            }
            unsigned bf[8][2];
            #pragma unroll
            for (int ni = 0; ni < 8; ni++) {
                int c = wn + ni * 8 + g;
                bf[ni][0] = Bs[(kb + tg) * 264 + c];
                bf[ni][1] = Bs[(kb + tg + 4) * 264 + c];
            }
            #pragma unroll
            for (int mi = 0; mi < 4; mi++)
                #pragma unroll
                for (int ni = 0; ni < 8; ni++) {
                    asm volatile(
                        "mma.sync.aligned.m16n8k8.row.col.f32.tf32.tf32.f32 "
                        "{%0,%1,%2,%3}, {%4,%5,%6,%7}, {%8,%9}, {%0,%1,%2,%3};"
                        : "+f"(acc[mi][ni][0]), "+f"(acc[mi][ni][1]),
                          "+f"(acc[mi][ni][2]), "+f"(acc[mi][ni][3])
                        : "r"(af[mi][0]), "r"(af[mi][1]), "r"(af[mi][2]), "r"(af[mi][3]),
                          "r"(bf[ni][0]), "r"(bf[ni][1]));
                }
        }
    }

    // epilogue: thread owns rows {g, g+8} per m-frag, cols tg*2,+1 per n-frag
    #pragma unroll
    for (int mi = 0; mi < 4; mi++) {
        #pragma unroll
        for (int half = 0; half < 2; half++) {
            int r = m0 + wm + mi * 16 + g + half * 8;
            size_t rowbase;
            if (MODE == 1) {
                int win = r >> 6, t = r & 63;
                int b_ = win >> 6;
                int hp = (((win >> 3) & 7) << 3) + (t >> 3);
                int wq_ = ((win & 7) << 3) + (t & 7);
                int hh = (hp + 4) & 63;
                int ww = (wq_ + 4) & 63;
                rowbase = ((size_t)b_ * 4096 + hh * 64 + ww) * 256;
            } else {
                rowbase = (size_t)r * ldc;
            }
            #pragma unroll
            for (int ni = 0; ni < 8; ni++) {
                int c = n0 + wn + ni * 8 + tg * 2;
                float v0 = acc[mi][ni][half * 2 + 0] + bias[c];
                float v1 = acc[mi][ni][half * 2 + 1] + bias[c + 1];
                float2 o;
                if (MODE == 0) {
                    o.x = v0; o.y = v1;
                } else if (MODE == 1 || MODE == 3) {
                    float2 sc = *(const float2*)(aux + rowbase + c);
                    o.x = v0 + sc.x; o.y = v1 + sc.y;
                } else { // MODE 2: exact gelu
                    o.x = 0.5f * v0 * (1.f + erff(v0 * 0.7071067811865476f));
                    o.y = 0.5f * v1 * (1.f + erff(v1 * 0.7071067811865476f));
                }
                *(float2*)(Cout + rowbase + c) = o;
            }
        }
    }
}

// ---------------- launcher ---------------------------------------------------
extern "C" void kernel_launch(void* const* d_in, const int* in_sizes, int n_in,
                              void* d_out, int out_size)
{
    const float* hid  = (const float*)d_in[0];
    const float* ln1g = (const float*)d_in[1];
    const float* ln1b = (const float*)d_in[2];
    const float* wq   = (const float*)d_in[3];
    const float* bq   = (const float*)d_in[4];
    const float* wk   = (const float*)d_in[5];
    const float* bk   = (const float*)d_in[6];
    const float* wv   = (const float*)d_in[7];
    const float* bv   = (const float*)d_in[8];
    const float* bt   = (const float*)d_in[9];
    const float* wo   = (const float*)d_in[10];
    const float* bo   = (const float*)d_in[11];
    const float* ln2g = (const float*)d_in[12];
    const float* ln2b = (const float*)d_in[13];
    const float* w1   = (const float*)d_in[14];
    const float* b1   = (const float*)d_in[15];
    const float* w2   = (const float*)d_in[16];
    const float* b2   = (const float*)d_in[17];
    float* out = (float*)d_out;

    float *p_xw, *p_qkv, *p_attn, *p_hs, *p_ff, *p_wqkv, *p_bqkv;
    cudaGetSymbolAddress((void**)&p_xw,   g_xw);
    cudaGetSymbolAddress((void**)&p_qkv,  g_qkv);
    cudaGetSymbolAddress((void**)&p_attn, g_attn);
    cudaGetSymbolAddress((void**)&p_hs,   g_hs);
    cudaGetSymbolAddress((void**)&p_ff,   g_ff);
    cudaGetSymbolAddress((void**)&p_wqkv, g_wqkv);
    cudaGetSymbolAddress((void**)&p_bqkv, g_bqkv);

    // 1. LN1 + shift + window partition
    ln_kernel<<<16384, 256>>>(hid, p_xw, ln1g, ln1b, 1);

    // 1b. pack QKV weights (tiny)
    pack_qkv_kernel<<<256, 256>>>(wq, wk, wv, bq, bk, bv, p_wqkv, p_bqkv);

    // 2. fused QKV projection (N=768)
    mma_gemm<0><<<dim3(3, 1024), 256>>>(p_xw, p_wqkv, p_bqkv, p_qkv, 256, 768, 768, nullptr);

    // 3. windowed attention
    attn_kernel<<<NWIN * NHEAD, 64>>>(p_qkv, bt, p_attn);

    // 4. output projection + reverse shift + residual
    mma_gemm<1><<<dim3(1, 1024), 256>>>(p_attn, wo, bo, p_hs, 256, 256, 256, hid);

    // 5. LN2
    ln_kernel<<<16384, 256>>>(p_hs, p_xw, ln2g, ln2b, 0);

    // 6. MLP up + GELU (N=1024)
    mma_gemm<2><<<dim3(4, 1024), 256>>>(p_xw, w1, b1, p_ff, 256, 1024, 1024, nullptr);

    // 7. MLP down + bias + residual -> output (K=1024)
    mma_gemm<3><<<dim3(1, 1024), 256>>>(p_ff, w2, b2, out, 1024, 256, 256, p_hs);
}

// round 4
// speedup vs baseline: 1.0009x; 1.0009x over previous
#include <cuda_runtime.h>
#include <math.h>

// Problem constants
#define MROWS  131072          // B * H * W = 32 * 64 * 64
#define CDIM   256
#define DFF    1024
#define NWIN   2048            // B * 64 windows
#define NHEAD  8

// ---------------- scratch ---------------------------------------------------
__device__ float g_xw  [(size_t)MROWS * CDIM];
__device__ float g_qkv [(size_t)MROWS * 768];
__device__ float g_attn[(size_t)MROWS * CDIM];
__device__ float g_hs  [(size_t)MROWS * CDIM];
__device__ float g_ff  [(size_t)MROWS * DFF];
__device__ float g_wqkv[256 * 768];
__device__ float g_bqkv[768];

// ---------------- tf32 helper ----------------------------------------------
__device__ __forceinline__ unsigned f2tf(float x) {
    unsigned r;
    asm("cvt.rna.tf32.f32 %0, %1;" : "=r"(r) : "f"(x));
    return r;
}

// ---------------- LayerNorm (+ optional shift/window partition) -------------
__global__ void ln_kernel(const float* __restrict__ x, float* __restrict__ y,
                          const float* __restrict__ gam, const float* __restrict__ bet,
                          int shift)
{
    int w    = (blockIdx.x * blockDim.x + threadIdx.x) >> 5;
    int lane = threadIdx.x & 31;
    if (w >= MROWS) return;

    size_t src;
    if (shift) {
        int b_  = w >> 12;
        int rem = w & 4095;
        int wi  = rem >> 6;
        int t   = rem & 63;
        int hp  = ((wi >> 3) << 3) + (t >> 3);
        int wp  = ((wi & 7)  << 3) + (t & 7);
        int sh  = (hp + 4) & 63;
        int sw  = (wp + 4) & 63;
        src = ((size_t)b_ * 4096 + sh * 64 + sw) * CDIM;
    } else {
        src = (size_t)w * CDIM;
    }

    float4 v0 = *(const float4*)(x + src + lane * 4);
    float4 v1 = *(const float4*)(x + src + 128 + lane * 4);

    float s  = v0.x + v0.y + v0.z + v0.w + v1.x + v1.y + v1.z + v1.w;
    float s2 = v0.x*v0.x + v0.y*v0.y + v0.z*v0.z + v0.w*v0.w
             + v1.x*v1.x + v1.y*v1.y + v1.z*v1.z + v1.w*v1.w;
    #pragma unroll
    for (int o = 16; o; o >>= 1) {
        s  += __shfl_xor_sync(0xffffffffu, s,  o);
        s2 += __shfl_xor_sync(0xffffffffu, s2, o);
    }
    float mean = s * (1.f / 256.f);
    float var  = s2 * (1.f / 256.f) - mean * mean;
    float rs   = rsqrtf(var + 1e-5f);

    float4 g0 = *(const float4*)(gam + lane * 4);
    float4 g1 = *(const float4*)(gam + 128 + lane * 4);
    float4 b0 = *(const float4*)(bet + lane * 4);
    float4 b1 = *(const float4*)(bet + 128 + lane * 4);

    float4 o0, o1;
    o0.x = (v0.x - mean) * rs * g0.x + b0.x;
    o0.y = (v0.y - mean) * rs * g0.y + b0.y;
    o0.z = (v0.z - mean) * rs * g0.z + b0.z;
    o0.w = (v0.w - mean) * rs * g0.w + b0.w;
    o1.x = (v1.x - mean) * rs * g1.x + b1.x;
    o1.y = (v1.y - mean) * rs * g1.y + b1.y;
    o1.z = (v1.z - mean) * rs * g1.z + b1.z;
    o1.w = (v1.w - mean) * rs * g1.w + b1.w;

    *(float4*)(y + (size_t)w * CDIM + lane * 4)       = o0;
    *(float4*)(y + (size_t)w * CDIM + 128 + lane * 4) = o1;
}

// ---------------- pack wq|wk|wv ---------------------------------------------
__global__ void pack_qkv_kernel(const float* __restrict__ wq, const float* __restrict__ wk,
                                const float* __restrict__ wv, const float* __restrict__ bq,
                                const float* __restrict__ bk, const float* __restrict__ bv,
                                float* __restrict__ w, float* __restrict__ b)
{
    int i = blockIdx.x * blockDim.x + threadIdx.x;   // 0..65535
    int k = i >> 8, n = i & 255;
    w[k * 768 + n]       = wq[i];
    w[k * 768 + 256 + n] = wk[i];
    w[k * 768 + 512 + n] = wv[i];
    if (k == 0) { b[n] = bq[n]; b[n + 256] = bk[n]; b[n + 512] = bv[n]; }
}

// ---------------- fused window attention ------------------------------------
__global__ void __launch_bounds__(64)
attn_kernel(const float* __restrict__ qkv, const float* __restrict__ bt,
            float* __restrict__ out)
{
    __shared__ float kS[64][32];
    __shared__ float vS[64][32];
    __shared__ float sS[64][65];
    __shared__ int   lab[64];

    int bx  = blockIdx.x;
    int win = bx >> 3;
    int h   = bx & 7;
    int t   = threadIdx.x;

    int r0 = t >> 3, c0 = t & 7;
    int hp = (((win >> 3) & 7) << 3) + r0;
    int wp = ((win & 7) << 3) + c0;
    lab[t] = (hp < 56 ? 0 : (hp < 60 ? 1 : 2)) * 3
           + (wp < 56 ? 0 : (wp < 60 ? 1 : 2));

    const float* base = qkv + (size_t)(win * 64 + t) * 768;
    float q[32];
    #pragma unroll
    for (int i = 0; i < 8; i++) ((float4*)q)[i] = *(const float4*)(base + h * 32 + i * 4);
    #pragma unroll
    for (int i = 0; i < 8; i++) *(float4*)&kS[t][i * 4] = *(const float4*)(base + 256 + h * 32 + i * 4);
    #pragma unroll
    for (int i = 0; i < 8; i++) *(float4*)&vS[t][i * 4] = *(const float4*)(base + 512 + h * 32 + i * 4);
    __syncthreads();

    const float scale = 0.1767766952966369f;
    float mx = -1e30f;
    int myLab = lab[t];
    for (int m = 0; m < 64; m++) {
        float d = 0.f;
        #pragma unroll
        for (int dd = 0; dd < 32; dd += 4) {
            float4 kv = *(const float4*)&kS[m][dd];
            d += q[dd] * kv.x + q[dd+1] * kv.y + q[dd+2] * kv.z + q[dd+3] * kv.w;
        }
        int r1 = m >> 3, c1 = m & 7;
        int idx = (r0 - r1 + 7) * 15 + (c0 - c1 + 7);
        float s = d * scale + bt[idx * 8 + h];
        if (myLab != lab[m]) s -= 100.f;
        sS[t][m] = s;
        mx = fmaxf(mx, s);
    }
    float sum = 0.f;
    for (int m = 0; m < 64; m++) {
        float e = __expf(sS[t][m] - mx);
        sS[t][m] = e;
        sum += e;
    }
    float inv = 1.f / sum;

    float acc[32];
    #pragma unroll
    for (int dd = 0; dd < 32; dd++) acc[dd] = 0.f;
    for (int m = 0; m < 64; m++) {
        float p = sS[t][m] * inv;
        #pragma unroll
        for (int dd = 0; dd < 32; dd += 4) {
            float4 vv = *(const float4*)&vS[m][dd];
            acc[dd]   += p * vv.x;
            acc[dd+1] += p * vv.y;
            acc[dd+2] += p * vv.z;
            acc[dd+3] += p * vv.w;
        }
    }
    float* o = out + (size_t)(win * 64 + t) * 256 + h * 32;
    #pragma unroll
    for (int i = 0; i < 8; i++) *(float4*)(o + i * 4) = ((float4*)acc)[i];
}

// ---------------- tf32 tensor-core GEMM with fused epilogues ----------------
// C(M,N) = A(M,K) @ B(K,N), row-major, fp32 in/out, tf32 mma accumulate fp32.
// Block tile 128x256, 8 warps, each warp 64x64 (4 m-frags x 8 n-frags), BK=16.
// MODE 0: + bias                          -> Cout (ldc)
// MODE 1: + bias + window-reverse/roll + shortcut(aux) -> image layout
// MODE 2: gelu(. + bias)                  -> Cout (ldc)
// MODE 3: + bias + aux[row]               -> Cout (ldc=256)
template<int MODE>
__global__ void __launch_bounds__(256, 1)
mma_gemm(const float* __restrict__ A, const float* __restrict__ Bw,
         const float* __restrict__ bias, float* __restrict__ Cout,
         int K, int ldb, int ldc, const float* __restrict__ aux)
{
    __shared__ unsigned As[128 * 20];   // [row][k], stride 20 (conflict-free frag loads)
    __shared__ unsigned Bs[16 * 264];   // [k][n],  stride 264

    int tid  = threadIdx.x;
    int lane = tid & 31, wid = tid >> 5;
    int g  = lane >> 2, tg = lane & 3;
    int wm = (wid & 1) * 64;
    int wn = (wid >> 1) * 64;
    int m0 = blockIdx.y * 128;
    int n0 = blockIdx.x * 256;

    float acc[4][8][4];
    #pragma unroll
    for (int mi = 0; mi < 4; mi++)
        #pragma unroll
        for (int ni = 0; ni < 8; ni++)
            #pragma unroll
            for (int r = 0; r < 4; r++) acc[mi][ni][r] = 0.f;

    int arow = tid >> 1, acol = (tid & 1) * 8;
    const float* Abase = A + (size_t)(m0 + arow) * K + acol;

    for (int k0 = 0; k0 < K; k0 += 16) {
        // global staging (overlaps previous tile's compute)
        float4 av0 = *(const float4*)(Abase + k0);
        float4 av1 = *(const float4*)(Abase + k0 + 4);
        float4 bv[4];
        #pragma unroll
        for (int i = 0; i < 4; i++) {
            int lin = tid + i * 256;
            int br = lin >> 6, bc = (lin & 63) * 4;
            bv[i] = *(const float4*)(Bw + (size_t)(k0 + br) * ldb + n0 + bc);
        }
        __syncthreads();
        {
            unsigned* ap = As + arow * 20 + acol;
            ap[0] = f2tf(av0.x); ap[1] = f2tf(av0.y); ap[2] = f2tf(av0.z); ap[3] = f2tf(av0.w);
            ap[4] = f2tf(av1.x); ap[5] = f2tf(av1.y); ap[6] = f2tf(av1.z); ap[7] = f2tf(av1.w);
            #pragma unroll
            for (int i = 0; i < 4; i++) {
                int lin = tid + i * 256;
                int br = lin >> 6, bc = (lin & 63) * 4;
                unsigned* bp = Bs + br * 264 + bc;
                bp[0] = f2tf(bv[i].x); bp[1] = f2tf(bv[i].y);
                bp[2] = f2tf(bv[i].z); bp[3] = f2tf(bv[i].w);
            }
        }
        __syncthreads();

        #pragma unroll
        for (int kf = 0; kf < 2; kf++) {
            int kb = kf * 8;
            unsigned af[4][4];
            #pragma unroll
            for (int mi = 0; mi < 4; mi++) {
                int r = wm + mi * 16 + g;
                af[mi][0] = As[r * 20 + kb + tg];
                af[mi][1] = As[(r + 8) * 20 + kb + tg];
                af[mi][2] = As[r * 20 + kb + tg + 4];
                af[mi][3] = As[(r + 8) * 20 + kb + tg + 4];
            }
            unsigned bf[8][2];
            #pragma unroll
            for (int ni = 0; ni < 8; ni++) {
                int c = wn + ni * 8 + g;
                bf[ni][0] = Bs[(kb + tg) * 264 + c];
                bf[ni][1] = Bs[(kb + tg + 4) * 264 + c];
            }
            #pragma unroll
            for (int mi = 0; mi < 4; mi++)
                #pragma unroll
                for (int ni = 0; ni < 8; ni++) {
                    asm volatile(
                        "mma.sync.aligned.m16n8k8.row.col.f32.tf32.tf32.f32 "
                        "{%0,%1,%2,%3}, {%4,%5,%6,%7}, {%8,%9}, {%0,%1,%2,%3};"
                        : "+f"(acc[mi][ni][0]), "+f"(acc[mi][ni][1]),
                          "+f"(acc[mi][ni][2]), "+f"(acc[mi][ni][3])
                        : "r"(af[mi][0]), "r"(af[mi][1]), "r"(af[mi][2]), "r"(af[mi][3]),
                          "r"(bf[ni][0]), "r"(bf[ni][1]));
                }
        }
    }

    // epilogue: thread owns rows {g, g+8} per m-frag, cols tg*2,+1 per n-frag
    #pragma unroll
    for (int mi = 0; mi < 4; mi++) {
        #pragma unroll
        for (int half = 0; half < 2; half++) {
            int r = m0 + wm + mi * 16 + g + half * 8;
            size_t rowbase;
            if (MODE == 1) {
                int win = r >> 6, t = r & 63;
                int b_ = win >> 6;
                int hp = (((win >> 3) & 7) << 3) + (t >> 3);
                int wq_ = ((win & 7) << 3) + (t & 7);
                int hh = (hp + 4) & 63;
                int ww = (wq_ + 4) & 63;
                rowbase = ((size_t)b_ * 4096 + hh * 64 + ww) * 256;
            } else {
                rowbase = (size_t)r * ldc;
            }
            #pragma unroll
            for (int ni = 0; ni < 8; ni++) {
                int c = n0 + wn + ni * 8 + tg * 2;
                float v0 = acc[mi][ni][half * 2 + 0] + bias[c];
                float v1 = acc[mi][ni][half * 2 + 1] + bias[c + 1];
                float2 o;
                if (MODE == 0) {
                    o.x = v0; o.y = v1;
                } else if (MODE == 1 || MODE == 3) {
                    float2 sc = *(const float2*)(aux + rowbase + c);
                    o.x = v0 + sc.x; o.y = v1 + sc.y;
                } else { // MODE 2: exact gelu
                    o.x = 0.5f * v0 * (1.f + erff(v0 * 0.7071067811865476f));
                    o.y = 0.5f * v1 * (1.f + erff(v1 * 0.7071067811865476f));
                }
                *(float2*)(Cout + rowbase + c) = o;
            }
        }
    }
}

// ---------------- launcher ---------------------------------------------------
extern "C" void kernel_launch(void* const* d_in, const int* in_sizes, int n_in,
                              void* d_out, int out_size)
{
    const float* hid  = (const float*)d_in[0];
    const float* ln1g = (const float*)d_in[1];
    const float* ln1b = (const float*)d_in[2];
    const float* wq   = (const float*)d_in[3];
    const float* bq   = (const float*)d_in[4];
    const float* wk   = (const float*)d_in[5];
    const float* bk   = (const float*)d_in[6];
    const float* wv   = (const float*)d_in[7];
    const float* bv   = (const float*)d_in[8];
    const float* bt   = (const float*)d_in[9];
    const float* wo   = (const float*)d_in[10];
    const float* bo   = (const float*)d_in[11];
    const float* ln2g = (const float*)d_in[12];
    const float* ln2b = (const float*)d_in[13];
    const float* w1   = (const float*)d_in[14];
    const float* b1   = (const float*)d_in[15];
    const float* w2   = (const float*)d_in[16];
    const float* b2   = (const float*)d_in[17];
    float* out = (float*)d_out;

    float *p_xw, *p_qkv, *p_attn, *p_hs, *p_ff, *p_wqkv, *p_bqkv;
    cudaGetSymbolAddress((void**)&p_xw,   g_xw);
    cudaGetSymbolAddress((void**)&p_qkv,  g_qkv);
    cudaGetSymbolAddress((void**)&p_attn, g_attn);
    cudaGetSymbolAddress((void**)&p_hs,   g_hs);
    cudaGetSymbolAddress((void**)&p_ff,   g_ff);
    cudaGetSymbolAddress((void**)&p_wqkv, g_wqkv);
    cudaGetSymbolAddress((void**)&p_bqkv, g_bqkv);

    // 1. LN1 + shift + window partition
    ln_kernel<<<16384, 256>>>(hid, p_xw, ln1g, ln1b, 1);

    // 1b. pack QKV weights (tiny)
    pack_qkv_kernel<<<256, 256>>>(wq, wk, wv, bq, bk, bv, p_wqkv, p_bqkv);

    // 2. fused QKV projection (N=768)
    mma_gemm<0><<<dim3(3, 1024), 256>>>(p_xw, p_wqkv, p_bqkv, p_qkv, 256, 768, 768, nullptr);

    // 3. windowed attention
    attn_kernel<<<NWIN * NHEAD, 64>>>(p_qkv, bt, p_attn);

    // 4. output projection + reverse shift + residual
    mma_gemm<1><<<dim3(1, 1024), 256>>>(p_attn, wo, bo, p_hs, 256, 256, 256, hid);

    // 5. LN2
    ln_kernel<<<16384, 256>>>(p_hs, p_xw, ln2g, ln2b, 0);

    // 6. MLP up + GELU (N=1024)
    mma_gemm<2><<<dim3(4, 1024), 256>>>(p_xw, w1, b1, p_ff, 256, 1024, 1024, nullptr);

    // 7. MLP down + bias + residual -> output (K=1024)
    mma_gemm<3><<<dim3(1, 1024), 256>>>(p_ff, w2, b2, out, 1024, 256, 256, p_hs);
}